// round 1
// baseline (speedup 1.0000x reference)
#include <cuda_runtime.h>
#include <math.h>

#define B_    16
#define CI    64
#define CO    64
#define NN    16384
#define MODES 2048
#define TEMBD 512
#define HN    8192   // NN/2, complex FFT length

// ---------------- scratch (device globals; no allocation allowed) ----------
__device__ float2 g_TW[HN];                 // exp(-2*pi*i*j/16384), j in [0,8192)
__device__ float  g_t[B_ * CI];             // temb projection
__device__ float2 g_xm[B_ * CI * MODES];    // 16 MB  x_ft[:, :, :modes] + t
__device__ float2 g_om[B_ * CO * MODES];    // 16 MB  einsum output

__device__ __forceinline__ float2 cmul(float2 a, float2 b) {
    return make_float2(a.x * b.x - a.y * b.y, a.x * b.y + a.y * b.x);
}

// ---------------- twiddle table ---------------------------------------------
__global__ void k_tw() {
    int j = blockIdx.x * blockDim.x + threadIdx.x;
    if (j < HN) {
        float s, c;
        // angle = -2*pi*j/16384 = -pi * (j/8192)
        sincospif(-(float)j / (float)HN, &s, &c);
        g_TW[j] = make_float2(c, s);
    }
}

// ---------------- temb projection: t[b,c] = silu(temb[b]) . dense_w[c] + db[c]
__global__ void k_temb(const float* __restrict__ temb,
                       const float* __restrict__ dw,
                       const float* __restrict__ db) {
    __shared__ float red[256];
    int b   = blockIdx.x;
    int tid = threadIdx.x;
    int c   = tid & 63;
    int sl  = tid >> 6;   // 0..3
    const float* te = temb + b * TEMBD;
    const float* w  = dw + c * TEMBD;
    float p = 0.f;
    int k0 = sl * 128;
    #pragma unroll 4
    for (int k = k0; k < k0 + 128; k++) {
        float v = te[k];
        float s = v / (1.0f + expf(-v));   // silu
        p += s * w[k];
    }
    red[tid] = p;
    __syncthreads();
    if (sl == 0)
        g_t[b * CI + c] = red[c] + red[c + 64] + red[c + 128] + red[c + 192] + db[c];
}

// ---------------- in-place radix-2 FFT of 8192 complex in shared memory ----
// 256 threads. INV=false: sum e^{-2pi i}, INV=true: sum e^{+2pi i} (unnormalized)
template <bool INV>
__device__ __forceinline__ void fft8192(float2* z, int tid) {
    // bit-reversal permutation (13 bits)
    for (int q = tid; q < HN; q += 256) {
        int j = __brev(q) >> 19;
        if (j > q) { float2 t = z[q]; z[q] = z[j]; z[j] = t; }
    }
    __syncthreads();
    #pragma unroll
    for (int s = 1; s <= 13; s++) {
        int half = 1 << (s - 1);
        for (int bf = tid; bf < (HN >> 1); bf += 256) {
            int pos = bf & (half - 1);
            int i1  = ((bf >> (s - 1)) << s) + pos;
            int i2  = i1 + half;
            float2 w = g_TW[pos << (14 - s)];   // exp(-2pi i pos/len)
            if (INV) w.y = -w.y;
            float2 u = z[i1];
            float2 v = cmul(z[i2], w);
            z[i1] = make_float2(u.x + v.x, u.y + v.y);
            z[i2] = make_float2(u.x - v.x, u.y - v.y);
        }
        __syncthreads();
    }
}

// ---------------- forward: real rfft (first 2048 bins) + temb bias ----------
__global__ void k_fwd(const float* __restrict__ x) {
    extern __shared__ unsigned char smem_u8[];
    float2* z = (float2*)smem_u8;
    int row = blockIdx.x;          // b*64 + ci
    int tid = threadIdx.x;

    // pack: z[q] = x[2q] + i x[2q+1]  (row is float2-aligned)
    const float2* xr = (const float2*)(x + (size_t)row * NN);
    for (int q = tid; q < HN; q += 256) z[q] = xr[q];
    __syncthreads();

    fft8192<false>(z, tid);

    float tb = g_t[row];
    float2* outp = g_xm + (size_t)row * MODES;
    for (int k = tid; k < MODES; k += 256) {
        float2 Zk = z[k];
        float2 Zm = z[(HN - k) & (HN - 1)];
        // E = 0.5(Zk + conj(Zm)); O = -0.5i(Zk - conj(Zm))
        float2 E = make_float2(0.5f * (Zk.x + Zm.x), 0.5f * (Zk.y - Zm.y));
        float2 O = make_float2(0.5f * (Zk.y + Zm.y), 0.5f * (Zm.x - Zk.x));
        float2 W = g_TW[k];                 // exp(-2pi i k/16384)
        float2 WO = cmul(W, O);
        outp[k] = make_float2(E.x + WO.x + tb, E.y + WO.y);
    }
}

// ---------------- einsum: out[b,o,m] = sum_i xm[b,i,m] * (wr+iwi)[i,o,m] ----
// grid 256 CTAs (8 modes each), 256 threads, thread tile 4b x 4o x 2m
__global__ void k_eins(const float* __restrict__ wr, const float* __restrict__ wi) {
    extern __shared__ unsigned char smem_u8[];
    float*  smf = (float*)smem_u8;
    float2* xs  = (float2*)smf;            // [i][b][mm] : 64*16*8 float2 = 64KB
    float*  wsr = smf + 2 * HN;            // [(ii*8+mm)*65 + o] : 2080 floats
    float*  wsi = wsr + 2080;

    int tid = threadIdx.x;
    int m0  = blockIdx.x * 8;
    int mg  = tid & 3;
    int og  = (tid >> 2) & 15;
    int bg  = tid >> 6;
    int b0  = bg * 4, o0 = og * 4, mm0 = mg * 2;

    // stage all x modes for this chunk: xm[(b*64+i)*2048 + m0+mm]
    for (int l = tid; l < 8192; l += 256) {
        int i  = l >> 7;
        int b  = (l >> 3) & 15;
        int mm = l & 7;
        xs[l] = g_xm[((size_t)(b * CI + i)) * MODES + m0 + mm];
    }

    float2 acc[4][4][2];
    #pragma unroll
    for (int a = 0; a < 4; a++)
        #pragma unroll
        for (int o = 0; o < 4; o++)
            #pragma unroll
            for (int m = 0; m < 2; m++) acc[a][o][m] = make_float2(0.f, 0.f);

    for (int ib = 0; ib < 16; ib++) {
        int i_base = ib * 4;
        // stage 4 i's of w (both components), 32B-contiguous global reads
        for (int l = tid; l < 2048; l += 256) {
            int ii = l >> 9;
            int o  = (l >> 3) & 63;
            int mm = l & 7;
            size_t g = ((size_t)(i_base + ii) * CO + o) * MODES + m0 + mm;
            int sidx = (ii * 8 + mm) * 65 + o;
            wsr[sidx] = wr[g];
            wsi[sidx] = wi[g];
        }
        __syncthreads();

        #pragma unroll
        for (int ii = 0; ii < 4; ii++) {
            int i = i_base + ii;
            float2 xv[4][2];
            #pragma unroll
            for (int bb = 0; bb < 4; bb++)
                #pragma unroll
                for (int t2 = 0; t2 < 2; t2++)
                    xv[bb][t2] = xs[i * 128 + (b0 + bb) * 8 + mm0 + t2];
            #pragma unroll
            for (int oo = 0; oo < 4; oo++) {
                #pragma unroll
                for (int t2 = 0; t2 < 2; t2++) {
                    int sidx = (ii * 8 + mm0 + t2) * 65 + o0 + oo;
                    float wrv = wsr[sidx];
                    float wiv = wsi[sidx];
                    #pragma unroll
                    for (int bb = 0; bb < 4; bb++) {
                        float2 xc = xv[bb][t2];
                        acc[bb][oo][t2].x += xc.x * wrv - xc.y * wiv;
                        acc[bb][oo][t2].y += xc.x * wiv + xc.y * wrv;
                    }
                }
            }
        }
        __syncthreads();
    }

    #pragma unroll
    for (int bb = 0; bb < 4; bb++)
        #pragma unroll
        for (int oo = 0; oo < 4; oo++)
            #pragma unroll
            for (int t2 = 0; t2 < 2; t2++)
                g_om[((size_t)(b0 + bb) * CO + (o0 + oo)) * MODES + m0 + mm0 + t2] =
                    acc[bb][oo][t2];
}

// ---------------- inverse: zero-padded irfft(n=16384) of 2048 modes ---------
__global__ void k_inv(float* __restrict__ out) {
    extern __shared__ unsigned char smem_u8[];
    float2* z = (float2*)smem_u8;
    int row = blockIdx.x;          // b*64 + co
    int tid = threadIdx.x;

    const float2* Y = g_om + (size_t)row * MODES;
    // Build even/odd-packed spectrum C[k] = A[k] + i*B[k]:
    //   A[k] = Yf[k] + Yf[k+HN],  B[k] = (Yf[k]-Yf[k+HN]) * e^{+2pi i k/16384}
    // with full spectrum Yf nonzero at k<2048 and mirrored conj at 16384-k.
    for (int k = tid; k < HN; k += 256) {
        float2 Yl = make_float2(0.f, 0.f);
        float2 Yh = make_float2(0.f, 0.f);
        if (k < MODES) {
            Yl = Y[k];
            if (k == 0) Yl.y = 0.f;    // c2r ignores imag(DC)
        }
        if (k > HN - MODES) {          // k in [6145, 8191]
            float2 ym = Y[HN - k];
            Yh = make_float2(ym.x, -ym.y);
        }
        float2 A  = make_float2(Yl.x + Yh.x, Yl.y + Yh.y);
        float2 Bc = make_float2(Yl.x - Yh.x, Yl.y - Yh.y);
        float2 w  = g_TW[k];
        w.y = -w.y;                    // e^{+2pi i k/16384}
        float2 Bv = cmul(Bc, w);
        z[k] = make_float2(A.x - Bv.y, A.y + Bv.x);
    }
    __syncthreads();

    fft8192<true>(z, tid);

    const float inv = 1.0f / (float)NN;
    float2* outp = (float2*)(out + (size_t)row * NN);
    for (int m = tid; m < HN; m += 256) {
        float2 g = z[m];
        outp[m] = make_float2(g.x * inv, g.y * inv);   // (y[2m], y[2m+1])
    }
}

// ---------------- launch ----------------------------------------------------
extern "C" void kernel_launch(void* const* d_in, const int* in_sizes, int n_in,
                              void* d_out, int out_size) {
    const float* x    = (const float*)d_in[0];
    const float* temb = (const float*)d_in[1];
    const float* wr   = (const float*)d_in[2];
    const float* wi   = (const float*)d_in[3];
    const float* dw   = (const float*)d_in[4];
    const float* db   = (const float*)d_in[5];
    float* out = (float*)d_out;

    cudaFuncSetAttribute(k_fwd,  cudaFuncAttributeMaxDynamicSharedMemorySize, 65536);
    cudaFuncSetAttribute(k_inv,  cudaFuncAttributeMaxDynamicSharedMemorySize, 65536);
    cudaFuncSetAttribute(k_eins, cudaFuncAttributeMaxDynamicSharedMemorySize, 82176);

    k_tw<<<32, 256>>>();
    k_temb<<<B_, 256>>>(temb, dw, db);
    k_fwd<<<B_ * CI, 256, 65536>>>(x);
    k_eins<<<MODES / 8, 256, 82176>>>(wr, wi);
    k_inv<<<B_ * CO, 256, 65536>>>(out);
}

// round 2
// speedup vs baseline: 1.8184x; 1.8184x over previous
#include <cuda_runtime.h>
#include <math.h>

#define B_    16
#define CI    64
#define CO    64
#define NN    16384
#define MODES 2048
#define TEMBD 512
#define HN    8192   // NN/2, complex FFT length

// ---------------- scratch (device globals; no allocation allowed) ----------
__device__ float2 g_TW[HN];                 // exp(-2*pi*i*j/16384), j in [0,8192)
__device__ float  g_t[B_ * CI];             // temb projection
__device__ float2 g_xm[B_ * CI * MODES];    // 16 MB  x_ft[:, :, :modes] + t
__device__ float2 g_om[B_ * CO * MODES];    // 16 MB  einsum output

__device__ __forceinline__ float2 cmul(float2 a, float2 b) {
    return make_float2(a.x * b.x - a.y * b.y, a.x * b.y + a.y * b.x);
}
__device__ __forceinline__ float2 cadd(float2 a, float2 b) {
    return make_float2(a.x + b.x, a.y + b.y);
}
__device__ __forceinline__ float2 csub(float2 a, float2 b) {
    return make_float2(a.x - b.x, a.y - b.y);
}

__host__ __device__ constexpr int brev5c(int i) {
    return ((i & 1) << 4) | ((i & 2) << 2) | (i & 4) | ((i & 8) >> 2) | ((i & 16) >> 4);
}
__host__ __device__ constexpr int brev3c(int i) {
    return ((i & 1) << 2) | (i & 2) | ((i & 4) >> 2);
}

// padded smem index: +1 float2 per 256 (kills stride-256 bank conflicts)
#define PADI(i) ((i) + ((i) >> 8))
#define SBUF_ELEMS (HN + 32)          // 8224 float2 = 65792 B

// ---------------- twiddle table ---------------------------------------------
__global__ void k_tw() {
    int j = blockIdx.x * blockDim.x + threadIdx.x;
    if (j < HN) {
        float s, c;
        sincospif(-(float)j / (float)HN, &s, &c);   // -2*pi*j/16384
        g_TW[j] = make_float2(c, s);
    }
}

// ---------------- temb projection -------------------------------------------
__global__ void k_temb(const float* __restrict__ temb,
                       const float* __restrict__ dw,
                       const float* __restrict__ db) {
    __shared__ float red[256];
    int b   = blockIdx.x;
    int tid = threadIdx.x;
    int c   = tid & 63;
    int sl  = tid >> 6;
    const float* te = temb + b * TEMBD;
    const float* w  = dw + c * TEMBD;
    float p = 0.f;
    int k0 = sl * 128;
    #pragma unroll 4
    for (int k = k0; k < k0 + 128; k++) {
        float v = te[k];
        p += (v / (1.0f + expf(-v))) * w[k];
    }
    red[tid] = p;
    __syncthreads();
    if (sl == 0)
        g_t[b * CI + c] = red[c] + red[c + 64] + red[c + 128] + red[c + 192] + db[c];
}

// ---------------- register DIF FFT (natural in, bit-reversed out) -----------
// stw[j] = W_32^j for forward (conjugated by caller for inverse)
template <int SIZE, int LOG>
__device__ __forceinline__ void fft_dif(float2* r, const float2* stw) {
    #pragma unroll
    for (int st = 0; st < LOG; st++) {
        const int span = SIZE >> (1 + st);
        #pragma unroll
        for (int g = 0; g < SIZE; g += 2 * span) {
            #pragma unroll
            for (int j = 0; j < span; j++) {
                float2 a = r[g + j];
                float2 b = r[g + j + span];
                r[g + j] = cadd(a, b);
                r[g + j + span] = cmul(csub(a, b), stw[j * (16 / span)]);
            }
        }
    }
}

// ---------------- four-step FFT-8192: 32(reg) x [32(reg) x 8(reg)] ----------
// Input : r[n1] = x[n1*256 + tid]  (caller preloads)
// Output: s[PADI(k)] = X[k] (forward) / sum e^{+2pi i} (inverse, unnormalized)
template <bool INV>
__device__ __forceinline__ void fft8192_4step(float2* s, const float2* stw,
                                              int tid, float2* r) {
    __syncthreads();   // protects s from previous use; stw ready

    // level 1: FFT-32 over n1 (stride 256), twiddle W_8192^{tid*k1}
    fft_dif<32, 5>(r, stw);
    float2 w1 = g_TW[2 * tid];               // W_8192^tid
    if (INV) w1.y = -w1.y;
    float2 wk = make_float2(1.f, 0.f);
    #pragma unroll
    for (int k1 = 0; k1 < 32; k1++) {
        s[k1 * 257 + tid] = cmul(r[brev5c(k1)], wk);
        wk = cmul(wk, w1);
    }
    __syncthreads();

    // level 2a: FFT-32 over n1' (stride 8 within each row), twiddle W_256^{n2'*k1'}
    const int k1 = tid & 31;
    const int n2p = tid >> 5;
    #pragma unroll
    for (int n1 = 0; n1 < 32; n1++)
        r[n1] = s[k1 * 257 + n1 * 8 + n2p];
    __syncthreads();
    fft_dif<32, 5>(r, stw);
    float2 w2 = g_TW[64 * n2p];              // W_256^{n2'}
    if (INV) w2.y = -w2.y;
    float2 wk2 = make_float2(1.f, 0.f);
    #pragma unroll
    for (int k1p = 0; k1p < 32; k1p++) {
        s[k1 * 257 + k1p * 8 + n2p] = cmul(r[brev5c(k1p)], wk2);
        wk2 = cmul(wk2, w2);
    }
    __syncthreads();

    // level 2b: FFT-8 over n2' ; final index k = k1 + 32*k1' + 1024*k2'
    #pragma unroll
    for (int rr = 0; rr < 4; rr++) {
        const int k1b = (tid >> 5) + 8 * rr;
        #pragma unroll
        for (int j = 0; j < 8; j++)
            r[rr * 8 + j] = s[(tid & 31) * 257 + k1b * 8 + j];
    }
    __syncthreads();
    #pragma unroll
    for (int rr = 0; rr < 4; rr++)
        fft_dif<8, 3>(r + rr * 8, stw);
    #pragma unroll
    for (int rr = 0; rr < 4; rr++) {
        const int base = (tid & 31) + 32 * ((tid >> 5) + 8 * rr);
        #pragma unroll
        for (int j = 0; j < 8; j++) {
            const int k = base + 1024 * brev3c(j);
            s[PADI(k)] = r[rr * 8 + j];
        }
    }
    __syncthreads();
}

// ---------------- forward: rfft (first 2048 bins) + temb bias ---------------
__global__ void k_fwd(const float* __restrict__ x) {
    extern __shared__ unsigned char smem_u8[];
    float2* s = (float2*)smem_u8;
    __shared__ float2 stw[16];
    int row = blockIdx.x;
    int tid = threadIdx.x;

    if (tid < 16) stw[tid] = g_TW[tid * 512];   // W_32^j

    const float2* xr = (const float2*)(x + (size_t)row * NN);
    float2 r[32];
    #pragma unroll
    for (int n1 = 0; n1 < 32; n1++) r[n1] = xr[n1 * 256 + tid];

    fft8192_4step<false>(s, stw, tid, r);

    float tb = g_t[row];
    float2* outp = g_xm + (size_t)row * MODES;
    #pragma unroll
    for (int k = tid; k < MODES; k += 256) {
        float2 Zk = s[PADI(k)];
        float2 Zm = s[PADI((HN - k) & (HN - 1))];
        float2 E = make_float2(0.5f * (Zk.x + Zm.x), 0.5f * (Zk.y - Zm.y));
        float2 O = make_float2(0.5f * (Zk.y + Zm.y), 0.5f * (Zm.x - Zk.x));
        float2 WO = cmul(g_TW[k], O);
        outp[k] = make_float2(E.x + WO.x + tb, E.y + WO.y);
    }
}

// ---------------- einsum: out[b,o,m] = sum_i xm[b,i,m] * (wr+iwi)[i,o,m] ----
__global__ void k_eins(const float* __restrict__ wr, const float* __restrict__ wi) {
    extern __shared__ unsigned char smem_u8[];
    float*  smf = (float*)smem_u8;
    float2* xs  = (float2*)smf;            // [i][b][mm] : 64*16*8 float2 = 64KB
    float*  wsr = smf + 2 * HN;            // [(ii*8+mm)*65 + o] : 2080 floats
    float*  wsi = wsr + 2080;

    int tid = threadIdx.x;
    int m0  = blockIdx.x * 8;
    int mg  = tid & 3;
    int og  = (tid >> 2) & 15;
    int bg  = tid >> 6;
    int b0  = bg * 4, o0 = og * 4, mm0 = mg * 2;

    // stage all x modes for this chunk
    for (int l = tid; l < 8192; l += 256) {
        int i  = l >> 7;
        int b  = (l >> 3) & 15;
        int mm = l & 7;
        xs[l] = g_xm[((size_t)(b * CI + i)) * MODES + m0 + mm];
    }

    // register prefetch of w chunk 0
    float pr[8], pi[8];
    #pragma unroll
    for (int k = 0; k < 8; k++) {
        int l  = tid + 256 * k;
        int ii = l >> 9, o = (l >> 3) & 63, mm = l & 7;
        size_t g = ((size_t)ii * CO + o) * MODES + m0 + mm;
        pr[k] = wr[g];
        pi[k] = wi[g];
    }

    float2 acc[4][4][2];
    #pragma unroll
    for (int a = 0; a < 4; a++)
        #pragma unroll
        for (int o = 0; o < 4; o++)
            #pragma unroll
            for (int m = 0; m < 2; m++) acc[a][o][m] = make_float2(0.f, 0.f);

    __syncthreads();   // xs staged, w smem free

    for (int ib = 0; ib < 16; ib++) {
        // store prefetched chunk to smem
        #pragma unroll
        for (int k = 0; k < 8; k++) {
            int l  = tid + 256 * k;
            int ii = l >> 9, o = (l >> 3) & 63, mm = l & 7;
            int sidx = (ii * 8 + mm) * 65 + o;
            wsr[sidx] = pr[k];
            wsi[sidx] = pi[k];
        }
        __syncthreads();   // chunk ready

        // prefetch next chunk (LDG latency hidden by compute below)
        if (ib < 15) {
            #pragma unroll
            for (int k = 0; k < 8; k++) {
                int l  = tid + 256 * k;
                int ii = l >> 9, o = (l >> 3) & 63, mm = l & 7;
                size_t g = ((size_t)((ib + 1) * 4 + ii) * CO + o) * MODES + m0 + mm;
                pr[k] = wr[g];
                pi[k] = wi[g];
            }
        }

        int i_base = ib * 4;
        #pragma unroll
        for (int ii = 0; ii < 4; ii++) {
            int i = i_base + ii;
            float2 xv[4][2];
            #pragma unroll
            for (int bb = 0; bb < 4; bb++)
                #pragma unroll
                for (int t2 = 0; t2 < 2; t2++)
                    xv[bb][t2] = xs[i * 128 + (b0 + bb) * 8 + mm0 + t2];
            #pragma unroll
            for (int oo = 0; oo < 4; oo++) {
                #pragma unroll
                for (int t2 = 0; t2 < 2; t2++) {
                    int sidx = (ii * 8 + mm0 + t2) * 65 + o0 + oo;
                    float wrv = wsr[sidx];
                    float wiv = wsi[sidx];
                    #pragma unroll
                    for (int bb = 0; bb < 4; bb++) {
                        float2 xc = xv[bb][t2];
                        acc[bb][oo][t2].x += xc.x * wrv - xc.y * wiv;
                        acc[bb][oo][t2].y += xc.x * wiv + xc.y * wrv;
                    }
                }
            }
        }
        __syncthreads();   // consumers done, buffer free for next store
    }

    #pragma unroll
    for (int bb = 0; bb < 4; bb++)
        #pragma unroll
        for (int oo = 0; oo < 4; oo++)
            #pragma unroll
            for (int t2 = 0; t2 < 2; t2++)
                g_om[((size_t)(b0 + bb) * CO + (o0 + oo)) * MODES + m0 + mm0 + t2] =
                    acc[bb][oo][t2];
}

// ---------------- inverse: zero-padded irfft(n=16384) of 2048 modes ---------
__global__ void k_inv(float* __restrict__ out) {
    extern __shared__ unsigned char smem_u8[];
    float2* s = (float2*)smem_u8;
    __shared__ float2 stw[16];
    int row = blockIdx.x;
    int tid = threadIdx.x;

    if (tid < 16) {
        float2 w = g_TW[tid * 512];
        stw[tid] = make_float2(w.x, -w.y);   // conj for inverse
    }

    const float2* Y = g_om + (size_t)row * MODES;
    // Build even/odd-packed spectrum C[k] = A[k] + i*B[k]
    for (int k = tid; k < HN; k += 256) {
        float2 Yl = make_float2(0.f, 0.f);
        float2 Yh = make_float2(0.f, 0.f);
        if (k < MODES) {
            Yl = Y[k];
            if (k == 0) Yl.y = 0.f;          // c2r ignores imag(DC)
        }
        if (k > HN - MODES) {                // k in [6145, 8191]
            float2 ym = Y[HN - k];
            Yh = make_float2(ym.x, -ym.y);
        }
        float2 A  = make_float2(Yl.x + Yh.x, Yl.y + Yh.y);
        float2 Bc = make_float2(Yl.x - Yh.x, Yl.y - Yh.y);
        float2 w  = g_TW[k];
        w.y = -w.y;                          // e^{+2pi i k/16384}
        float2 Bv = cmul(Bc, w);
        s[PADI(k)] = make_float2(A.x - Bv.y, A.y + Bv.x);
    }
    __syncthreads();

    float2 r[32];
    #pragma unroll
    for (int n1 = 0; n1 < 32; n1++)
        r[n1] = s[n1 * 257 + tid];           // PADI(n1*256+tid)

    fft8192_4step<true>(s, stw, tid, r);

    const float inv = 1.0f / (float)NN;
    float2* outp = (float2*)(out + (size_t)row * NN);
    #pragma unroll
    for (int m = tid; m < HN; m += 256) {
        float2 g = s[PADI(m)];
        outp[m] = make_float2(g.x * inv, g.y * inv);
    }
}

// ---------------- launch ----------------------------------------------------
extern "C" void kernel_launch(void* const* d_in, const int* in_sizes, int n_in,
                              void* d_out, int out_size) {
    const float* x    = (const float*)d_in[0];
    const float* temb = (const float*)d_in[1];
    const float* wr   = (const float*)d_in[2];
    const float* wi   = (const float*)d_in[3];
    const float* dw   = (const float*)d_in[4];
    const float* db   = (const float*)d_in[5];
    float* out = (float*)d_out;

    const int fft_smem = SBUF_ELEMS * sizeof(float2);   // 65792
    cudaFuncSetAttribute(k_fwd,  cudaFuncAttributeMaxDynamicSharedMemorySize, fft_smem);
    cudaFuncSetAttribute(k_inv,  cudaFuncAttributeMaxDynamicSharedMemorySize, fft_smem);
    cudaFuncSetAttribute(k_eins, cudaFuncAttributeMaxDynamicSharedMemorySize, 82176);

    k_tw<<<32, 256>>>();
    k_temb<<<B_, 256>>>(temb, dw, db);
    k_fwd<<<B_ * CI, 256, fft_smem>>>(x);
    k_eins<<<MODES / 8, 256, 82176>>>(wr, wi);
    k_inv<<<B_ * CO, 256, fft_smem>>>(out);
}